// round 11
// baseline (speedup 1.0000x reference)
#include <cuda_runtime.h>
#include <math.h>
#include <float.h>

#define NBATCH 16
#define NANCH  5
#define NHH    96
#define NWW    96
#define MAXT   50
#define NCLS   40
#define CH     45
#define TSTR   53
#define NCELL  (NHH*NWW)                 // 9216
#define NALL   (NBATCH*NANCH*NCELL)      // 737280
#define NSLOT  (MAXT*NANCH)              // 250 per batch
#define CONF_GRID   720
#define CONF_BLOCK  256
#define CONF_THREADS (CONF_GRID*CONF_BLOCK)   // 184320; NALL/CONF_THREADS == 4 exactly
#define TAIL_GRID   250
#define TAIL_BLOCK  512                  // 16 warps/block; 250*16 = 4000 warps = NBATCH*NSLOT
#define NFQ 9   // Sx Sy Sw Sh Sce maskB corrB subPc bceAll
#define NIQ 5   // corrCnt nM nProp nCorrect nGT

struct TRec { int label; float tx, ty, tw, th; };

__device__ TRec  g_trec[NBATCH*MAXT];
__device__ int   g_slot[NBATCH*NSLOT];   // packed: cell|a<<14|wt<<17|type<<23 (0 = none)
__device__ float g_confPart[CONF_GRID];  // overwritten every run — no init needed
__device__ int   g_propPart[CONF_GRID];
__device__ int   g_ncPart[NBATCH];
__device__ float g_bpF[NFQ][TAIL_GRID];  // K2 block partials (overwritten every run)
__device__ int   g_bpI[NIQ][TAIL_GRID];
__device__ int   g_done2;

__device__ __forceinline__ float softplusf(float x) {
    return fmaxf(x, 0.0f) + log1pf(expf(-fabsf(x)));
}

// ================= K1: conf partials (all blocks) + targets/resolve (blocks 0..15) =========
// VERBATIM R10 k_mega.
__global__ void __launch_bounds__(CONF_BLOCK, 8) k_mega(const float* __restrict__ pred,
                                                        const float* __restrict__ tgt,
                                                        const int*   __restrict__ ts) {
    if (blockIdx.x == 0 && threadIdx.x == 0) g_done2 = 0;

    // ---- conf plane: exactly 4 elements per thread, independent loads, per-block partial ----
    {
        int tid = blockIdx.x * blockDim.x + threadIdx.x;   // 0 .. 184319
        float s = 0.f; int c = 0;
        #pragma unroll
        for (int k = 0; k < 4; k++) {
            const float* ap = pred + (size_t)(tid + k * CONF_THREADS) * CH;
            float pc;
            asm volatile("ld.global.nc.L2::64B.f32 %0, [%1];" : "=f"(pc) : "l"(ap));
            s += softplusf(pc);
            c += (pc > 0.f);
        }
        for (int off = 16; off; off >>= 1) {
            s += __shfl_down_sync(0xffffffffu, s, off);
            c += __shfl_down_sync(0xffffffffu, c, off);
        }
        __shared__ float ws[8]; __shared__ int wc[8];
        int lane = threadIdx.x & 31, wid = threadIdx.x >> 5;
        if (lane == 0) { ws[wid] = s; wc[wid] = c; }
        __syncthreads();
        if (wid == 0) {
            s = (lane < 8) ? ws[lane] : 0.f;
            c = (lane < 8) ? wc[lane] : 0;
            for (int off = 4; off; off >>= 1) {
                s += __shfl_down_sync(0xffffffffu, s, off);
                c += __shfl_down_sync(0xffffffffu, c, off);
            }
            if (lane == 0) { g_confPart[blockIdx.x] = s; g_propPart[blockIdx.x] = c; }
        }
    }

    // ---- fat path: block b < 16 handles batch b entirely ----
    if (blockIdx.x < NBATCH) {
        int b = blockIdx.x;
        int n = ts[b];
        __shared__ int sc[MAXT], sb[MAXT], si[MAXT];
        __shared__ int s_nc;
        if (threadIdx.x == 0) s_nc = 0;
        __syncthreads();

        int t = threadIdx.x;
        if (t < n) {
            const float aw[NANCH] = {1.f, 2.f, 4.f, 2.f, 4.f};
            const float ah[NANCH] = {1.f, 2.f, 4.f, 4.f, 2.f};
            const float* row = tgt + (size_t)(b * MAXT + t) * TSTR;

            float lv = -FLT_MAX; int label = 0;
            #pragma unroll
            for (int c = 0; c < NCLS; c++) {
                float v = row[13 + c];
                if (v > lv) { lv = v; label = c; }
            }

            float gx = row[0] * 0.0625f;
            float gy = row[1] * 0.0625f;
            float gh = row[3] * 0.0625f;
            float gw = row[4] * 0.0625f;
            int gi = (int)gx;
            int gj = (int)gy;

            float best_iou = -1.f; int best = 0; int ign = 0;
            #pragma unroll
            for (int a = 0; a < NANCH; a++) {
                float inter = fmaxf(fminf(gw, aw[a]) + 1.f, 0.f) * fmaxf(fminf(gh, ah[a]) + 1.f, 0.f);
                float denom = (gw + 1.f) * (gh + 1.f) + (aw[a] + 1.f) * (ah[a] + 1.f) - inter + 1e-16f;
                float iou = inter / denom;
                if (iou > best_iou) { best_iou = iou; best = a; }
                if (iou > 0.5f) ign |= (1 << a);
            }

            const float* p = pred + (size_t)(((b * NANCH + best) * NHH + gj) * NWW + gi) * CH;
            float cv = -FLT_MAX; int ci = 0;
            #pragma unroll
            for (int c = 0; c < NCLS; c++) {
                float v = p[5 + c];
                if (v > cv) { cv = v; ci = c; }
            }

            float pc = p[0], px = p[1], py = p[2], ph = p[3], pw = p[4];
            float pbx = px + (float)gi;
            float pby = py + (float)gj;
            float pbw = expf(pw) * aw[best];
            float pbh = expf(ph) * ah[best];

            float gx1 = gx - gw * 0.5f, gx2 = gx + gw * 0.5f;
            float gy1 = gy - gh * 0.5f, gy2 = gy + gh * 0.5f;
            float px1 = pbx - pbw * 0.5f, px2 = pbx + pbw * 0.5f;
            float py1 = pby - pbh * 0.5f, py2 = pby + pbh * 0.5f;
            float iw = fmaxf(fminf(gx2, px2) - fmaxf(gx1, px1) + 1.f, 0.f);
            float ih = fmaxf(fminf(gy2, py2) - fmaxf(gy1, py1) + 1.f, 0.f);
            float inter = iw * ih;
            float ga = (gx2 - gx1 + 1.f) * (gy2 - gy1 + 1.f);
            float pa = (px2 - px1 + 1.f) * (py2 - py1 + 1.f);
            float iou = inter / (ga + pa - inter + 1e-16f);

            if (iou > 0.5f && ci == label && pc > 0.5f) atomicAdd(&s_nc, 1);

            sc[t] = gj * NWW + gi;
            sb[t] = best;
            si[t] = ign;
            TRec r;
            r.label = label;
            r.tx = gx - (float)gi;
            r.ty = gy - (float)gj;
            r.tw = logf(gw / aw[best] + 1e-16f);
            r.th = logf(gh / ah[best] + 1e-16f);
            g_trec[b * MAXT + t] = r;
        }
        __syncthreads();

        int s = threadIdx.x;              // (t, a) pair index
        if (s < NSLOT) {
            int out = 0;
            int tt = s / NANCH, a = s % NANCH;
            if (tt < n) {
                int mycell = sc[tt];
                bool firstOcc = true;
                for (int u = 0; u < tt; u++) if (sc[u] == mycell) { firstOcc = false; break; }
                if (firstOcc) {
                    int Bv = -1, Iv = -1;
                    for (int u = 0; u < n; u++) {
                        if (sc[u] == mycell) {
                            if ((si[u] >> a) & 1) Iv = u;
                            if (sb[u] == a)       Bv = u;
                        }
                    }
                    int type;
                    if (Bv < 0) type = (Iv < 0) ? 0 : 1;      // 1: cmf==0 (ignored, not best)
                    else        type = (Iv <= Bv) ? 2 : 3;     // 2: winner; 3: mask=1,conf=0
                    if (type)
                        out = mycell | (a << 14) | ((type == 2 ? Bv : 0) << 17) | (type << 23);
                }
            }
            g_slot[b * NSLOT + s] = out;
        }
        if (threadIdx.x == 0) g_ncPart[b] = s_nc;
    }
}

// ================= K2: warp-per-slot tail + last-block finalize =========
__global__ void __launch_bounds__(TAIL_BLOCK) k_tail(const float* __restrict__ pred,
                                                     const int*   __restrict__ ts,
                                                     float* __restrict__ out, int out_size) {
    int tid  = threadIdx.x;
    int lane = tid & 31;
    int wid  = tid >> 5;                              // 0..15
    int gwarp   = blockIdx.x * (TAIL_BLOCK >> 5) + wid;  // 0..3999 == slot index
    int gthread = blockIdx.x * TAIL_BLOCK + tid;

    float fv[NFQ] = {0.f,0.f,0.f,0.f,0.f,0.f,0.f,0.f,0.f};
    int   iv[NIQ] = {0,0,0,0,0};

    // fold conf partials / nc / ts (each entry claimed by exactly one global thread)
    if (gthread < CONF_GRID) { fv[8] = g_confPart[gthread]; iv[2] = g_propPart[gthread]; }
    if (gthread < NBATCH)    { iv[3] = g_ncPart[gthread];   iv[4] = ts[gthread]; }

    // one slot per warp
    {
        int v = g_slot[gwarp];
        if (v) {
            int b    = gwarp / NSLOT;
            int cell = v & 0x3FFF;
            int a    = (v >> 14) & 7;
            int wt   = (v >> 17) & 63;
            int type = (v >> 23) & 3;

            const float* p = pred + (size_t)((b * NANCH + a) * NCELL + cell) * CH;

            if (type == 2) {
                // lane-parallel softmax over 40 classes
                float v1 = p[5 + lane];                                   // c = 0..31
                float v2 = (lane < 8) ? p[37 + lane] : -FLT_MAX;          // c = 32..39
                float m = fmaxf(v1, v2);
                #pragma unroll
                for (int off = 16; off; off >>= 1)
                    m = fmaxf(m, __shfl_xor_sync(0xffffffffu, m, off));
                float e = __expf(v1 - m) + ((lane < 8) ? __expf(v2 - m) : 0.f);
                #pragma unroll
                for (int off = 16; off; off >>= 1)
                    e += __shfl_xor_sync(0xffffffffu, e, off);

                if (lane == 0) {
                    float pc = p[0];
                    float sp = softplusf(pc);
                    fv[6] += sp; iv[0] += 1;
                    fv[5] += sp - pc; iv[1] += 1;
                    TRec r = g_trec[b * MAXT + wt];
                    float dx = p[1] - r.tx, dy = p[2] - r.ty;
                    float dh = p[3] - r.th, dw = p[4] - r.tw;
                    fv[0] += dx * dx;
                    fv[1] += dy * dy;
                    fv[2] += dw * dw;
                    fv[3] += dh * dh;
                    fv[4] += m + __logf(e) - p[5 + r.label];
                }
            } else if (lane == 0) {
                float pc = p[0];
                if (type == 3) {
                    fv[7] += pc;                      // cmf=1, tconf=1
                } else {
                    fv[6] += softplusf(pc);           // type1: cmf==0
                    iv[0] += 1;
                }
            }
        }
    }

    // block reduce: full warp shuffle (conf partial folds live on arbitrary lanes)
    #pragma unroll
    for (int off = 16; off; off >>= 1) {
        #pragma unroll
        for (int q = 0; q < NFQ; q++) fv[q] += __shfl_down_sync(0xffffffffu, fv[q], off);
        #pragma unroll
        for (int q = 0; q < NIQ; q++) iv[q] += __shfl_down_sync(0xffffffffu, iv[q], off);
    }
    __shared__ float sf[NFQ][16];
    __shared__ int   si2[NIQ][16];
    if (lane == 0) {
        #pragma unroll
        for (int q = 0; q < NFQ; q++) sf[q][wid] = fv[q];
        #pragma unroll
        for (int q = 0; q < NIQ; q++) si2[q][wid] = iv[q];
    }
    __syncthreads();
    if (wid == 0) {
        #pragma unroll
        for (int q = 0; q < NFQ; q++) fv[q] = (lane < 16) ? sf[q][lane] : 0.f;
        #pragma unroll
        for (int q = 0; q < NIQ; q++) iv[q] = (lane < 16) ? si2[q][lane] : 0;
        #pragma unroll
        for (int off = 8; off; off >>= 1) {
            #pragma unroll
            for (int q = 0; q < NFQ; q++) fv[q] += __shfl_down_sync(0xffffffffu, fv[q], off);
            #pragma unroll
            for (int q = 0; q < NIQ; q++) iv[q] += __shfl_down_sync(0xffffffffu, iv[q], off);
        }
        if (lane == 0) {
            #pragma unroll
            for (int q = 0; q < NFQ; q++) g_bpF[q][blockIdx.x] = fv[q];
            #pragma unroll
            for (int q = 0; q < NIQ; q++) g_bpI[q][blockIdx.x] = iv[q];
        }
    }

    // last-block ticket
    __syncthreads();
    __shared__ int isLast;
    if (tid == 0) {
        __threadfence();
        isLast = (atomicAdd(&g_done2, 1) == TAIL_GRID - 1) ? 1 : 0;
    }
    __syncthreads();
    if (!isLast || wid != 0) return;

    // warp 0 of last block: strided sum over 250 block partials
    __threadfence();
    float ff[NFQ] = {0.f,0.f,0.f,0.f,0.f,0.f,0.f,0.f,0.f};
    int   ii[NIQ] = {0,0,0,0,0};
    for (int i = lane; i < TAIL_GRID; i += 32) {
        #pragma unroll
        for (int q = 0; q < NFQ; q++) ff[q] += g_bpF[q][i];
        #pragma unroll
        for (int q = 0; q < NIQ; q++) ii[q] += g_bpI[q][i];
    }
    #pragma unroll
    for (int off = 16; off; off >>= 1) {
        #pragma unroll
        for (int q = 0; q < NFQ; q++) ff[q] += __shfl_down_sync(0xffffffffu, ff[q], off);
        #pragma unroll
        for (int q = 0; q < NIQ; q++) ii[q] += __shfl_down_sync(0xffffffffu, ii[q], off);
    }
    if (lane == 0) {
        int nGT = ii[4];
        float nM = (float)ii[1];
        float lx = ff[0] / nM, ly = ff[1] / nM, lw = ff[2] / nM, lh = ff[3] / nM;
        float coord = lx + ly + lw + lh;
        float cmfB = ff[8] - ff[6] - ff[7];
        float cmfC = (float)(NALL - ii[0]);
        float lconf = cmfB / cmfC + ff[5] / nM;
        float lcls  = (1.0f / NBATCH) * ff[4] / nM;
        float loss  = coord + lconf + lcls;
        float nCor  = (float)ii[3];
        int   gtd   = nGT > 1 ? nGT : 1;
        float recall = nCor / (float)gtd;
        float nProp = (float)ii[2];
        float prec  = (nProp > 0.f) ? (nCor / fmaxf(nProp, 1.f)) : 1.f;
        if (out_size >= 6) {
            out[0] = loss; out[1] = coord; out[2] = lconf;
            out[3] = lcls; out[4] = recall; out[5] = prec;
        }
    }
}

extern "C" void kernel_launch(void* const* d_in, const int* in_sizes, int n_in,
                              void* d_out, int out_size) {
    const float* pred = (const float*)d_in[0];
    const float* tgt  = (const float*)d_in[1];
    const int*   ts   = (const int*)d_in[2];
    float* out = (float*)d_out;

    k_mega<<<CONF_GRID, CONF_BLOCK>>>(pred, tgt, ts);
    k_tail<<<TAIL_GRID, TAIL_BLOCK>>>(pred, ts, out, out_size);
}

// round 13
// speedup vs baseline: 1.1405x; 1.1405x over previous
#include <cuda_runtime.h>
#include <math.h>
#include <float.h>

#define NBATCH 16
#define NANCH  5
#define NHH    96
#define NWW    96
#define MAXT   50
#define NCLS   40
#define CH     45
#define TSTR   53
#define NCELL  (NHH*NWW)                 // 9216
#define NALL   (NBATCH*NANCH*NCELL)      // 737280
#define NSLOT  (MAXT*NANCH)              // 250 per batch
#define CONF_GRID   720
#define CONF_BLOCK  256
#define CONF_THREADS (CONF_GRID*CONF_BLOCK)   // 184320; NALL/CONF_THREADS == 4 exactly
#define TAIL_GRID   125
#define TAIL_BLOCK  1024                 // 32 warps/block; 125*32 = 4000 warps = NBATCH*NSLOT
#define NFQ 9   // Sx Sy Sw Sh Sce maskB corrB subPc bceAll
#define NIQ 5   // corrCnt nM nProp nCorrect nGT

struct TRec { int label; float tx, ty, tw, th; };

__device__ TRec  g_trec[NBATCH*MAXT];
__device__ int   g_slot[NBATCH*NSLOT];   // packed: cell|a<<14|wt<<17|type<<23 (0 = none)
__device__ float g_confPart[CONF_GRID];  // overwritten every run — no init needed
__device__ int   g_propPart[CONF_GRID];
__device__ int   g_ncPart[NBATCH];
__device__ float g_bpF[NFQ][TAIL_GRID];  // K2 block partials (overwritten every run)
__device__ int   g_bpI[NIQ][TAIL_GRID];
__device__ int   g_done2;

__device__ __forceinline__ float softplusf(float x) {
    return fmaxf(x, 0.0f) + log1pf(expf(-fabsf(x)));
}

// ================= K1: conf partials (all blocks) + targets/resolve (blocks 0..15) =========
// VERBATIM R10/R11 k_mega.
__global__ void __launch_bounds__(CONF_BLOCK, 8) k_mega(const float* __restrict__ pred,
                                                        const float* __restrict__ tgt,
                                                        const int*   __restrict__ ts) {
    if (blockIdx.x == 0 && threadIdx.x == 0) g_done2 = 0;

    // ---- conf plane: exactly 4 elements per thread, independent loads, per-block partial ----
    {
        int tid = blockIdx.x * blockDim.x + threadIdx.x;   // 0 .. 184319
        float s = 0.f; int c = 0;
        #pragma unroll
        for (int k = 0; k < 4; k++) {
            const float* ap = pred + (size_t)(tid + k * CONF_THREADS) * CH;
            float pc;
            asm volatile("ld.global.nc.L2::64B.f32 %0, [%1];" : "=f"(pc) : "l"(ap));
            s += softplusf(pc);
            c += (pc > 0.f);
        }
        for (int off = 16; off; off >>= 1) {
            s += __shfl_down_sync(0xffffffffu, s, off);
            c += __shfl_down_sync(0xffffffffu, c, off);
        }
        __shared__ float ws[8]; __shared__ int wc[8];
        int lane = threadIdx.x & 31, wid = threadIdx.x >> 5;
        if (lane == 0) { ws[wid] = s; wc[wid] = c; }
        __syncthreads();
        if (wid == 0) {
            s = (lane < 8) ? ws[lane] : 0.f;
            c = (lane < 8) ? wc[lane] : 0;
            for (int off = 4; off; off >>= 1) {
                s += __shfl_down_sync(0xffffffffu, s, off);
                c += __shfl_down_sync(0xffffffffu, c, off);
            }
            if (lane == 0) { g_confPart[blockIdx.x] = s; g_propPart[blockIdx.x] = c; }
        }
    }

    // ---- fat path: block b < 16 handles batch b entirely ----
    if (blockIdx.x < NBATCH) {
        int b = blockIdx.x;
        int n = ts[b];
        __shared__ int sc[MAXT], sb[MAXT], si[MAXT];
        __shared__ int s_nc;
        if (threadIdx.x == 0) s_nc = 0;
        __syncthreads();

        int t = threadIdx.x;
        if (t < n) {
            const float aw[NANCH] = {1.f, 2.f, 4.f, 2.f, 4.f};
            const float ah[NANCH] = {1.f, 2.f, 4.f, 4.f, 2.f};
            const float* row = tgt + (size_t)(b * MAXT + t) * TSTR;

            float lv = -FLT_MAX; int label = 0;
            #pragma unroll
            for (int c = 0; c < NCLS; c++) {
                float v = row[13 + c];
                if (v > lv) { lv = v; label = c; }
            }

            float gx = row[0] * 0.0625f;
            float gy = row[1] * 0.0625f;
            float gh = row[3] * 0.0625f;
            float gw = row[4] * 0.0625f;
            int gi = (int)gx;
            int gj = (int)gy;

            float best_iou = -1.f; int best = 0; int ign = 0;
            #pragma unroll
            for (int a = 0; a < NANCH; a++) {
                float inter = fmaxf(fminf(gw, aw[a]) + 1.f, 0.f) * fmaxf(fminf(gh, ah[a]) + 1.f, 0.f);
                float denom = (gw + 1.f) * (gh + 1.f) + (aw[a] + 1.f) * (ah[a] + 1.f) - inter + 1e-16f;
                float iou = inter / denom;
                if (iou > best_iou) { best_iou = iou; best = a; }
                if (iou > 0.5f) ign |= (1 << a);
            }

            const float* p = pred + (size_t)(((b * NANCH + best) * NHH + gj) * NWW + gi) * CH;
            float cv = -FLT_MAX; int ci = 0;
            #pragma unroll
            for (int c = 0; c < NCLS; c++) {
                float v = p[5 + c];
                if (v > cv) { cv = v; ci = c; }
            }

            float pc = p[0], px = p[1], py = p[2], ph = p[3], pw = p[4];
            float pbx = px + (float)gi;
            float pby = py + (float)gj;
            float pbw = expf(pw) * aw[best];
            float pbh = expf(ph) * ah[best];

            float gx1 = gx - gw * 0.5f, gx2 = gx + gw * 0.5f;
            float gy1 = gy - gh * 0.5f, gy2 = gy + gh * 0.5f;
            float px1 = pbx - pbw * 0.5f, px2 = pbx + pbw * 0.5f;
            float py1 = pby - pbh * 0.5f, py2 = pby + pbh * 0.5f;
            float iw = fmaxf(fminf(gx2, px2) - fmaxf(gx1, px1) + 1.f, 0.f);
            float ih = fmaxf(fminf(gy2, py2) - fmaxf(gy1, py1) + 1.f, 0.f);
            float inter = iw * ih;
            float ga = (gx2 - gx1 + 1.f) * (gy2 - gy1 + 1.f);
            float pa = (px2 - px1 + 1.f) * (py2 - py1 + 1.f);
            float iou = inter / (ga + pa - inter + 1e-16f);

            if (iou > 0.5f && ci == label && pc > 0.5f) atomicAdd(&s_nc, 1);

            sc[t] = gj * NWW + gi;
            sb[t] = best;
            si[t] = ign;
            TRec r;
            r.label = label;
            r.tx = gx - (float)gi;
            r.ty = gy - (float)gj;
            r.tw = logf(gw / aw[best] + 1e-16f);
            r.th = logf(gh / ah[best] + 1e-16f);
            g_trec[b * MAXT + t] = r;
        }
        __syncthreads();

        int s = threadIdx.x;              // (t, a) pair index
        if (s < NSLOT) {
            int out = 0;
            int tt = s / NANCH, a = s % NANCH;
            if (tt < n) {
                int mycell = sc[tt];
                bool firstOcc = true;
                for (int u = 0; u < tt; u++) if (sc[u] == mycell) { firstOcc = false; break; }
                if (firstOcc) {
                    int Bv = -1, Iv = -1;
                    for (int u = 0; u < n; u++) {
                        if (sc[u] == mycell) {
                            if ((si[u] >> a) & 1) Iv = u;
                            if (sb[u] == a)       Bv = u;
                        }
                    }
                    int type;
                    if (Bv < 0) type = (Iv < 0) ? 0 : 1;      // 1: cmf==0 (ignored, not best)
                    else        type = (Iv <= Bv) ? 2 : 3;     // 2: winner; 3: mask=1,conf=0
                    if (type)
                        out = mycell | (a << 14) | ((type == 2 ? Bv : 0) << 17) | (type << 23);
                }
            }
            g_slot[b * NSLOT + s] = out;
        }
        if (threadIdx.x == 0) g_ncPart[b] = s_nc;
    }
}

// ================= K2: warp-per-slot tail (125 x 1024) + last-block finalize =========
__global__ void __launch_bounds__(TAIL_BLOCK) k_tail(const float* __restrict__ pred,
                                                     const int*   __restrict__ ts,
                                                     float* __restrict__ out, int out_size) {
    int tid  = threadIdx.x;
    int lane = tid & 31;
    int wid  = tid >> 5;                                 // 0..31
    int gwarp = blockIdx.x * (TAIL_BLOCK >> 5) + wid;    // 0..3999 == slot index

    // slot-side accumulators (lane 0 only holds nonzero)
    float sx=0.f, sy=0.f, sw_=0.f, sh=0.f, sce=0.f, maskB=0.f, corrB=0.f, subPc=0.f;
    int   corrC=0, nM=0;
    // fold-side accumulators (block 0 only; scattered across lanes)
    float bceAll=0.f; int nProp=0, nCor=0, nGT=0;

    if (blockIdx.x == 0) {
        if (tid < CONF_GRID) { bceAll = g_confPart[tid]; nProp = g_propPart[tid]; }
        if (tid < NBATCH)    { nCor = g_ncPart[tid]; nGT = ts[tid]; }
        // reduce the 4 fold quantities to lane 0 of each warp
        #pragma unroll
        for (int off = 16; off; off >>= 1) {
            bceAll += __shfl_down_sync(0xffffffffu, bceAll, off);
            nProp  += __shfl_down_sync(0xffffffffu, nProp, off);
            nCor   += __shfl_down_sync(0xffffffffu, nCor, off);
            nGT    += __shfl_down_sync(0xffffffffu, nGT, off);
        }
    }

    // one slot per warp
    {
        int v = g_slot[gwarp];
        if (v) {
            int b    = gwarp / NSLOT;
            int cell = v & 0x3FFF;
            int a    = (v >> 14) & 7;
            int wt   = (v >> 17) & 63;
            int type = (v >> 23) & 3;

            const float* p = pred + (size_t)((b * NANCH + a) * NCELL + cell) * CH;

            if (type == 2) {
                // lane-parallel softmax over 40 classes
                float v1 = p[5 + lane];                                   // c = 0..31
                float v2 = (lane < 8) ? p[37 + lane] : -FLT_MAX;          // c = 32..39
                float m = fmaxf(v1, v2);
                #pragma unroll
                for (int off = 16; off; off >>= 1)
                    m = fmaxf(m, __shfl_xor_sync(0xffffffffu, m, off));
                float e = __expf(v1 - m) + ((lane < 8) ? __expf(v2 - m) : 0.f);
                #pragma unroll
                for (int off = 16; off; off >>= 1)
                    e += __shfl_xor_sync(0xffffffffu, e, off);

                if (lane == 0) {
                    float pc = p[0];
                    float sp = softplusf(pc);
                    corrB += sp; corrC += 1;
                    maskB += sp - pc; nM += 1;
                    TRec r = g_trec[b * MAXT + wt];
                    float dx = p[1] - r.tx, dy = p[2] - r.ty;
                    float dh = p[3] - r.th, dw = p[4] - r.tw;
                    sx += dx * dx;
                    sy += dy * dy;
                    sw_ += dw * dw;
                    sh += dh * dh;
                    sce += m + __logf(e) - p[5 + r.label];
                }
            } else if (lane == 0) {
                float pc = p[0];
                if (type == 3) {
                    subPc += pc;                      // cmf=1, tconf=1
                } else {
                    corrB += softplusf(pc);           // type1: cmf==0
                    corrC += 1;
                }
            }
        }
    }

    // cross-warp stage: lane 0 of each warp writes 14 quantities to smem
    __shared__ float sf[NFQ][32];
    __shared__ int   si2[NIQ][32];
    if (lane == 0) {
        sf[0][wid]=sx; sf[1][wid]=sy; sf[2][wid]=sw_; sf[3][wid]=sh; sf[4][wid]=sce;
        sf[5][wid]=maskB; sf[6][wid]=corrB; sf[7][wid]=subPc; sf[8][wid]=bceAll;
        si2[0][wid]=corrC; si2[1][wid]=nM; si2[2][wid]=nProp; si2[3][wid]=nCor; si2[4][wid]=nGT;
    }
    __syncthreads();
    if (wid == 0) {
        float fv[NFQ]; int iv[NIQ];
        #pragma unroll
        for (int q = 0; q < NFQ; q++) fv[q] = sf[q][lane];
        #pragma unroll
        for (int q = 0; q < NIQ; q++) iv[q] = si2[q][lane];
        #pragma unroll
        for (int off = 16; off; off >>= 1) {
            #pragma unroll
            for (int q = 0; q < NFQ; q++) fv[q] += __shfl_down_sync(0xffffffffu, fv[q], off);
            #pragma unroll
            for (int q = 0; q < NIQ; q++) iv[q] += __shfl_down_sync(0xffffffffu, iv[q], off);
        }
        if (lane == 0) {
            #pragma unroll
            for (int q = 0; q < NFQ; q++) g_bpF[q][blockIdx.x] = fv[q];
            #pragma unroll
            for (int q = 0; q < NIQ; q++) g_bpI[q][blockIdx.x] = iv[q];
        }
    }

    // last-block ticket
    __syncthreads();
    __shared__ int isLast;
    if (tid == 0) {
        __threadfence();
        isLast = (atomicAdd(&g_done2, 1) == TAIL_GRID - 1) ? 1 : 0;
    }
    __syncthreads();
    if (!isLast || wid != 0) return;

    // warp 0 of last block: strided sum over 125 block partials
    __threadfence();
    float ff[NFQ] = {0.f,0.f,0.f,0.f,0.f,0.f,0.f,0.f,0.f};
    int   ii[NIQ] = {0,0,0,0,0};
    for (int i = lane; i < TAIL_GRID; i += 32) {
        #pragma unroll
        for (int q = 0; q < NFQ; q++) ff[q] += g_bpF[q][i];
        #pragma unroll
        for (int q = 0; q < NIQ; q++) ii[q] += g_bpI[q][i];
    }
    #pragma unroll
    for (int off = 16; off; off >>= 1) {
        #pragma unroll
        for (int q = 0; q < NFQ; q++) ff[q] += __shfl_down_sync(0xffffffffu, ff[q], off);
        #pragma unroll
        for (int q = 0; q < NIQ; q++) ii[q] += __shfl_down_sync(0xffffffffu, ii[q], off);
    }
    if (lane == 0) {
        int nGTt = ii[4];
        float fnM = (float)ii[1];
        float lx = ff[0] / fnM, ly = ff[1] / fnM, lw = ff[2] / fnM, lh = ff[3] / fnM;
        float coord = lx + ly + lw + lh;
        float cmfB = ff[8] - ff[6] - ff[7];
        float cmfC = (float)(NALL - ii[0]);
        float lconf = cmfB / cmfC + ff[5] / fnM;
        float lcls  = (1.0f / NBATCH) * ff[4] / fnM;
        float loss  = coord + lconf + lcls;
        float fnCor = (float)ii[3];
        int   gtd   = nGTt > 1 ? nGTt : 1;
        float recall = fnCor / (float)gtd;
        float fnProp = (float)ii[2];
        float prec  = (fnProp > 0.f) ? (fnCor / fmaxf(fnProp, 1.f)) : 1.f;
        if (out_size >= 6) {
            out[0] = loss; out[1] = coord; out[2] = lconf;
            out[3] = lcls; out[4] = recall; out[5] = prec;
        }
    }
}

extern "C" void kernel_launch(void* const* d_in, const int* in_sizes, int n_in,
                              void* d_out, int out_size) {
    const float* pred = (const float*)d_in[0];
    const float* tgt  = (const float*)d_in[1];
    const int*   ts   = (const int*)d_in[2];
    float* out = (float*)d_out;

    k_mega<<<CONF_GRID, CONF_BLOCK>>>(pred, tgt, ts);
    k_tail<<<TAIL_GRID, TAIL_BLOCK>>>(pred, ts, out, out_size);
}